// round 1
// baseline (speedup 1.0000x reference)
#include <cuda_runtime.h>
#include <stdint.h>

#define HW 64
#define NPIX (4 * 64 * 64)   // 16384 pixels

// Ping-pong coordinate buffers + results (float2 = (x, y) per pixel)
__device__ float2 g_bufA[NPIX];
__device__ float2 g_bufB[NPIX];
__device__ float2 g_resf[NPIX];
__device__ float2 g_resb[NPIX];

// ---------------------------------------------------------------------------
// Threefry-2x32 (matches jax._src.prng.threefry2x32)
// ---------------------------------------------------------------------------
__device__ __forceinline__ uint32_t rotl32(uint32_t v, int r) {
    return (v << r) | (v >> (32 - r));
}

__device__ __forceinline__ void tf4(uint32_t& x0, uint32_t& x1,
                                    int r0, int r1, int r2, int r3) {
    x0 += x1; x1 = rotl32(x1, r0); x1 ^= x0;
    x0 += x1; x1 = rotl32(x1, r1); x1 ^= x0;
    x0 += x1; x1 = rotl32(x1, r2); x1 ^= x0;
    x0 += x1; x1 = rotl32(x1, r3); x1 ^= x0;
}

__device__ __forceinline__ void threefry2x32(uint32_t k0, uint32_t k1,
                                             uint32_t c0, uint32_t c1,
                                             uint32_t& o0, uint32_t& o1) {
    uint32_t ks2 = k0 ^ k1 ^ 0x1BD11BDAu;
    uint32_t x0 = c0 + k0;
    uint32_t x1 = c1 + k1;
    tf4(x0, x1, 13, 15, 26, 6);   x0 += k1;  x1 += ks2 + 1u;
    tf4(x0, x1, 17, 29, 16, 24);  x0 += ks2; x1 += k0  + 2u;
    tf4(x0, x1, 13, 15, 26, 6);   x0 += k0;  x1 += k1  + 3u;
    tf4(x0, x1, 17, 29, 16, 24);  x0 += k1;  x1 += ks2 + 4u;
    tf4(x0, x1, 13, 15, 26, 6);   x0 += ks2; x1 += k0  + 5u;
    o0 = x0; o1 = x1;
}

// Derive the subkey for (handle fwd/bwd, random-search index 0..2).
// root = jax.random.key(42) -> data (0, 42)
// kf, kb = split(root): counts iota(4) paired as (0,2),(1,3):
//   kf = (o0(0,2), o0(1,3)),  kb = (o1(0,2), o1(1,3))
// k1,k2,k3 = split(k, 3): counts iota(6) paired (0,3),(1,4),(2,5):
//   concat -> [a0,a1,a2,b0,b1,b2]; k1=(a0,a1), k2=(a2,b0), k3=(b1,b2)
__device__ __forceinline__ void get_rs_key(int fwd, int rs,
                                           uint32_t& K0, uint32_t& K1) {
    uint32_t a0, b0, a1, b1;
    threefry2x32(0u, 42u, 0u, 2u, a0, b0);
    threefry2x32(0u, 42u, 1u, 3u, a1, b1);
    uint32_t hk0 = fwd ? a0 : b0;
    uint32_t hk1 = fwd ? a1 : b1;

    uint32_t p0a, p0b, p1a, p1b, p2a, p2b;
    threefry2x32(hk0, hk1, 0u, 3u, p0a, p0b);
    threefry2x32(hk0, hk1, 1u, 4u, p1a, p1b);
    threefry2x32(hk0, hk1, 2u, 5u, p2a, p2b);
    if (rs == 0)      { K0 = p0a; K1 = p1a; }
    else if (rs == 1) { K0 = p2a; K1 = p0b; }
    else              { K0 = p1b; K1 = p2b; }
}

// random bits for flat element index e in [0, 32768): pairs (e, e+16384)
__device__ __forceinline__ uint32_t random_bits(uint32_t K0, uint32_t K1, uint32_t e) {
    uint32_t o0, o1;
    if (e < 16384u) { threefry2x32(K0, K1, e, e + 16384u, o0, o1); return o0; }
    else            { threefry2x32(K0, K1, e - 16384u, e, o0, o1); return o1; }
}

// jax.random.normal semantics: uniform in [lo, 1) via mantissa bits, then
// sqrt(2) * erfinv(u) using XLA's Giles polynomial (w = -log1p(-x*x)).
__device__ __forceinline__ float normal_from_bits(uint32_t bits) {
    float f = __uint_as_float((bits >> 9) | 0x3f800000u) - 1.0f; // [0,1)
    const float lo = -0.99999994f;           // nextafter(-1, 0)
    float u = fmaxf(lo, f * 2.0f + lo);      // (1 - lo) rounds to 2.0f
    float w = -log1pf(-u * u);
    float p;
    if (w < 5.0f) {
        w = w - 2.5f;
        p = 2.81022636e-08f;
        p = 3.43273939e-07f + p * w;
        p = -3.5233877e-06f + p * w;
        p = -4.39150654e-06f + p * w;
        p = 0.00021858087f + p * w;
        p = -0.00125372503f + p * w;
        p = -0.00417768164f + p * w;
        p = 0.246640727f + p * w;
        p = 1.50140941f + p * w;
    } else {
        w = sqrtf(w) - 3.0f;
        p = -0.000200214257f;
        p = 0.000100950558f + p * w;
        p = 0.00134934322f + p * w;
        p = -0.00367342844f + p * w;
        p = 0.00573950773f + p * w;
        p = -0.0076224613f + p * w;
        p = 0.00943887047f + p * w;
        p = 1.00167406f + p * w;
        p = 2.83297682f + p * w;
    }
    return 1.41421356f * (p * u);   // sqrt(2) rounds to 0x3FB504F3
}

// ---------------------------------------------------------------------------
// Score: bilinear sample of this pixel's 64x64 correlation slice.
// forward:  corr[(((b*64+h)*64+w)*64 + y)*64 + x]  -> base + y*64 + x
// backward: corr[(((b*64+y)*64+x)*64 + h)*64 + w]  -> base + y*262144 + x*4096
// ---------------------------------------------------------------------------
__device__ __forceinline__ float score(const float* __restrict__ base,
                                       int sy, int sx, float x, float y) {
    float x0f = floorf(x), y0f = floorf(y);
    float wx = x - x0f, wy = y - y0f;
    int x0i = min(max((int)x0f, 0), 63);
    int x1i = min(x0i + 1, 63);
    int y0i = min(max((int)y0f, 0), 63);
    int y1i = min(y0i + 1, 63);
    float v00 = __ldg(base + y0i * sy + x0i * sx);
    float v01 = __ldg(base + y0i * sy + x1i * sx);
    float v10 = __ldg(base + y1i * sy + x0i * sx);
    float v11 = __ldg(base + y1i * sy + x1i * sx);
    return v00 * (1.0f - wx) * (1.0f - wy) + v01 * wx * (1.0f - wy)
         + v10 * (1.0f - wx) * wy          + v11 * wx * wy;
}

__device__ __forceinline__ const float* corr_base(const float* __restrict__ corr,
                                                  int p, int b, int h, int w,
                                                  int fwd, int& sy, int& sx) {
    if (fwd) { sy = 64; sx = 1; return corr + (size_t)p * 4096; }
    sy = 262144; sx = 4096;
    return corr + (size_t)b * 16777216 + h * 64 + w;
}

// ---------------------------------------------------------------------------
// Kernels
// ---------------------------------------------------------------------------
__global__ void init_kernel(const float* __restrict__ m, float2* __restrict__ dst) {
    int p = blockIdx.x * blockDim.x + threadIdx.x;
    if (p >= NPIX) return;
    int b = p >> 12, hw = p & 4095;
    dst[p] = make_float2(m[b * 8192 + hw], m[b * 8192 + 4096 + hw]);
}

__global__ void prop_kernel(const float* __restrict__ corr,
                            const float2* __restrict__ src,
                            float2* __restrict__ dst,
                            int dx, int dy, int fwd) {
    int p = blockIdx.x * blockDim.x + threadIdx.x;
    if (p >= NPIX) return;
    int b = p >> 12, h = (p >> 6) & 63, w = p & 63;
    int sy, sx;
    const float* base = corr_base(corr, p, b, h, w, fwd, sy, sx);

    float2 best = src[p];
    float best_s = score(base, sy, sx, best.x, best.y);

    // horizontal candidate: roll(coords, dx, axis=W) + (dx, 0), clamp
    int wsrc = (w - dx) & 63;
    float2 ch = src[(p & ~63) | wsrc];
    ch.x = fminf(fmaxf(ch.x + (float)dx, 0.0f), 63.0f);
    ch.y = fminf(fmaxf(ch.y, 0.0f), 63.0f);
    float s = score(base, sy, sx, ch.x, ch.y);
    if (s > best_s) best = ch;
    best_s = fmaxf(s, best_s);

    // vertical candidate: roll(coords, dy, axis=H) + (0, dy), clamp
    int hsrc = (h - dy) & 63;
    float2 cv = src[(b << 12) | (hsrc << 6) | w];
    cv.y = fminf(fmaxf(cv.y + (float)dy, 0.0f), 63.0f);
    cv.x = fminf(fmaxf(cv.x, 0.0f), 63.0f);
    s = score(base, sy, sx, cv.x, cv.y);
    if (s > best_s) best = cv;

    dst[p] = best;
}

__global__ void rs_kernel(const float* __restrict__ corr,
                          const float2* __restrict__ src,
                          float2* __restrict__ dst,
                          int fwd, int rsIdx) {
    int p = blockIdx.x * blockDim.x + threadIdx.x;
    if (p >= NPIX) return;
    int b = p >> 12, h = (p >> 6) & 63, w = p & 63;
    int sy, sx;
    const float* base = corr_base(corr, p, b, h, w, fwd, sy, sx);

    uint32_t K0, K1;
    get_rs_key(fwd, rsIdx, K0, K1);
    float n0 = normal_from_bits(random_bits(K0, K1, 2u * (uint32_t)p));
    float n1 = normal_from_bits(random_bits(K0, K1, 2u * (uint32_t)p + 1u));

    float2 c = src[p];
    float2 cn;
    cn.x = fminf(fmaxf(c.x + 3.0f * n0, 0.0f), 63.0f);
    cn.y = fminf(fmaxf(c.y + 3.0f * n1, 0.0f), 63.0f);

    float old_s = score(base, sy, sx, c.x, c.y);
    float new_s = score(base, sy, sx, cn.x, cn.y);
    bool upd = (new_s - 1.0f * old_s) > 0.0f;
    dst[p] = upd ? cn : c;
}

__global__ void final_kernel(const float* __restrict__ mf, float* __restrict__ out) {
    int p = blockIdx.x * blockDim.x + threadIdx.x;
    if (p >= NPIX) return;
    int b = p >> 12, hw = p & 4095;

    float2 f = g_resf[p];
    // bilinear sample of res_b (as B,H,W,2 image) at res_f coords
    float x0f = floorf(f.x), y0f = floorf(f.y);
    float wx = f.x - x0f, wy = f.y - y0f;
    int x0i = min(max((int)x0f, 0), 63);
    int x1i = min(x0i + 1, 63);
    int y0i = min(max((int)y0f, 0), 63);
    int y1i = min(y0i + 1, 63);
    const float2* img = g_resb + (b << 12);
    float2 v00 = img[y0i * 64 + x0i];
    float2 v01 = img[y0i * 64 + x1i];
    float2 v10 = img[y1i * 64 + x0i];
    float2 v11 = img[y1i * 64 + x1i];
    float cx = v00.x * (1.0f - wx) * (1.0f - wy) + v01.x * wx * (1.0f - wy)
             + v10.x * (1.0f - wx) * wy          + v11.x * wx * wy;
    float cy = v00.y * (1.0f - wx) * (1.0f - wy) + v01.y * wx * (1.0f - wy)
             + v10.y * (1.0f - wx) * wy          + v11.y * wx * wy;

    float diff = fmaxf(fabsf(f.x - cx), fabsf(f.y - cy));
    bool invalid = diff > 0.01f;
    float ox = invalid ? mf[b * 8192 + hw]        : f.x;
    float oy = invalid ? mf[b * 8192 + 4096 + hw] : f.y;
    out[b * 8192 + hw]        = ox;
    out[b * 8192 + 4096 + hw] = oy;
}

// ---------------------------------------------------------------------------
// Host launcher
// ---------------------------------------------------------------------------
extern "C" void kernel_launch(void* const* d_in, const int* in_sizes, int n_in,
                              void* d_out, int out_size) {
    const float* mf   = (const float*)d_in[0];
    const float* mb   = (const float*)d_in[1];
    const float* corr = (const float*)d_in[2];
    float* out = (float*)d_out;

    float2 *A, *B, *RF, *RB;
    cudaGetSymbolAddress((void**)&A,  g_bufA);
    cudaGetSymbolAddress((void**)&B,  g_bufB);
    cudaGetSymbolAddress((void**)&RF, g_resf);
    cudaGetSymbolAddress((void**)&RB, g_resb);

    const int TB = 256;
    const int GB = NPIX / TB;

    // ---- forward handle (corr_f) ----
    init_kernel<<<GB, TB>>>(mf, A);
    prop_kernel<<<GB, TB>>>(corr, A, B,  1,  1, 1);
    rs_kernel  <<<GB, TB>>>(corr, B, A, 1, 0);
    prop_kernel<<<GB, TB>>>(corr, A, B, -1, -1, 1);
    rs_kernel  <<<GB, TB>>>(corr, B, A, 1, 1);
    prop_kernel<<<GB, TB>>>(corr, A, B, -1,  1, 1);
    rs_kernel  <<<GB, TB>>>(corr, B, A, 1, 2);
    prop_kernel<<<GB, TB>>>(corr, A, RF, 1, -1, 1);

    // ---- backward handle (corr_b = transposed view, no materialization) ----
    init_kernel<<<GB, TB>>>(mb, A);
    prop_kernel<<<GB, TB>>>(corr, A, B,  1,  1, 0);
    rs_kernel  <<<GB, TB>>>(corr, B, A, 0, 0);
    prop_kernel<<<GB, TB>>>(corr, A, B, -1, -1, 0);
    rs_kernel  <<<GB, TB>>>(corr, B, A, 0, 1);
    prop_kernel<<<GB, TB>>>(corr, A, B, -1,  1, 0);
    rs_kernel  <<<GB, TB>>>(corr, B, A, 0, 2);
    prop_kernel<<<GB, TB>>>(corr, A, RB, 1, -1, 0);

    // ---- forward-backward consistency + output transpose ----
    final_kernel<<<GB, TB>>>(mf, out);
}

// round 3
// speedup vs baseline: 2.2632x; 2.2632x over previous
#include <cuda_runtime.h>
#include <stdint.h>

#define NPIX 16384   // 4 * 64 * 64 pixels per handle

// Per-handle ping-pong state: (x, y, score, unused) per pixel
__device__ float4 g_st[2][2][NPIX];
__device__ float2 g_res[2][NPIX];          // [0]=res_f, [1]=res_b

// ---------------------------------------------------------------------------
// Threefry-2x32 (matches jax._src.prng.threefry2x32)
// ---------------------------------------------------------------------------
__device__ __forceinline__ uint32_t rotl32(uint32_t v, int r) {
    return (v << r) | (v >> (32 - r));
}

__device__ __forceinline__ void tf4(uint32_t& x0, uint32_t& x1,
                                    int r0, int r1, int r2, int r3) {
    x0 += x1; x1 = rotl32(x1, r0); x1 ^= x0;
    x0 += x1; x1 = rotl32(x1, r1); x1 ^= x0;
    x0 += x1; x1 = rotl32(x1, r2); x1 ^= x0;
    x0 += x1; x1 = rotl32(x1, r3); x1 ^= x0;
}

__device__ __forceinline__ void threefry2x32(uint32_t k0, uint32_t k1,
                                             uint32_t c0, uint32_t c1,
                                             uint32_t& o0, uint32_t& o1) {
    uint32_t ks2 = k0 ^ k1 ^ 0x1BD11BDAu;
    uint32_t x0 = c0 + k0;
    uint32_t x1 = c1 + k1;
    tf4(x0, x1, 13, 15, 26, 6);   x0 += k1;  x1 += ks2 + 1u;
    tf4(x0, x1, 17, 29, 16, 24);  x0 += ks2; x1 += k0  + 2u;
    tf4(x0, x1, 13, 15, 26, 6);   x0 += k0;  x1 += k1  + 3u;
    tf4(x0, x1, 17, 29, 16, 24);  x0 += k1;  x1 += ks2 + 4u;
    tf4(x0, x1, 13, 15, 26, 6);   x0 += ks2; x1 += k0  + 5u;
    o0 = x0; o1 = x1;
}

// Subkey for (handle fwd/bwd, random-search index 0..2)
__device__ __forceinline__ void get_rs_key(int fwd, int rs,
                                           uint32_t& K0, uint32_t& K1) {
    uint32_t a0, b0, a1, b1;
    threefry2x32(0u, 42u, 0u, 2u, a0, b0);
    threefry2x32(0u, 42u, 1u, 3u, a1, b1);
    uint32_t hk0 = fwd ? a0 : b0;
    uint32_t hk1 = fwd ? a1 : b1;

    uint32_t p0a, p0b, p1a, p1b, p2a, p2b;
    threefry2x32(hk0, hk1, 0u, 3u, p0a, p0b);
    threefry2x32(hk0, hk1, 1u, 4u, p1a, p1b);
    threefry2x32(hk0, hk1, 2u, 5u, p2a, p2b);
    if (rs == 0)      { K0 = p0a; K1 = p1a; }
    else if (rs == 1) { K0 = p2a; K1 = p0b; }
    else              { K0 = p1b; K1 = p2b; }
}

// random bits for flat element index e in [0, 32768): pairs (e, e+16384)
__device__ __forceinline__ uint32_t random_bits(uint32_t K0, uint32_t K1, uint32_t e) {
    uint32_t o0, o1;
    if (e < 16384u) { threefry2x32(K0, K1, e, e + 16384u, o0, o1); return o0; }
    else            { threefry2x32(K0, K1, e - 16384u, e, o0, o1); return o1; }
}

// jax.random.normal: uniform via mantissa bits, then sqrt(2)*erfinv (XLA Giles poly)
__device__ __forceinline__ float normal_from_bits(uint32_t bits) {
    float f = __uint_as_float((bits >> 9) | 0x3f800000u) - 1.0f; // [0,1)
    const float lo = -0.99999994f;
    float u = fmaxf(lo, f * 2.0f + lo);
    float w = -log1pf(-u * u);
    float p;
    if (w < 5.0f) {
        w = w - 2.5f;
        p = 2.81022636e-08f;
        p = 3.43273939e-07f + p * w;
        p = -3.5233877e-06f + p * w;
        p = -4.39150654e-06f + p * w;
        p = 0.00021858087f + p * w;
        p = -0.00125372503f + p * w;
        p = -0.00417768164f + p * w;
        p = 0.246640727f + p * w;
        p = 1.50140941f + p * w;
    } else {
        w = sqrtf(w) - 3.0f;
        p = -0.000200214257f;
        p = 0.000100950558f + p * w;
        p = 0.00134934322f + p * w;
        p = -0.00367342844f + p * w;
        p = 0.00573950773f + p * w;
        p = -0.0076224613f + p * w;
        p = 0.00943887047f + p * w;
        p = 1.00167406f + p * w;
        p = 2.83297682f + p * w;
    }
    return 1.41421356f * (p * u);
}

// ---------------------------------------------------------------------------
// Bilinear score on this pixel's 64x64 correlation slice.
// forward:  base = corr + p*4096,              sy=64,     sx=1
// backward: base = corr + b*16M + h*64 + w,    sy=262144, sx=4096
// ---------------------------------------------------------------------------
__device__ __forceinline__ float score(const float* __restrict__ base,
                                       int sy, int sx, float x, float y) {
    float x0f = floorf(x), y0f = floorf(y);
    float wx = x - x0f, wy = y - y0f;
    int x0i = min(max((int)x0f, 0), 63);
    int x1i = min(x0i + 1, 63);
    int y0i = min(max((int)y0f, 0), 63);
    int y1i = min(y0i + 1, 63);
    float v00 = __ldg(base + y0i * sy + x0i * sx);
    float v01 = __ldg(base + y0i * sy + x1i * sx);
    float v10 = __ldg(base + y1i * sy + x0i * sx);
    float v11 = __ldg(base + y1i * sy + x1i * sx);
    return v00 * (1.0f - wx) * (1.0f - wy) + v01 * wx * (1.0f - wy)
         + v10 * (1.0f - wx) * wy          + v11 * wx * wy;
}

// ---------------------------------------------------------------------------
// Fused stage kernel: propagate (+ random search unless last stage).
// Grid = 128 blocks x 256 threads; blocks [0,64)=forward, [64,128)=backward.
//   stage0: read incumbent + neighbor coords directly from input m
//   else:   read (coords, score) float4 from src
//   last:   no rs; write float2 result to g_res
// ---------------------------------------------------------------------------
__global__ void __launch_bounds__(256)
stage_kernel(const float* __restrict__ mf, const float* __restrict__ mb,
             const float* __restrict__ corr,
             const float4* __restrict__ srcF, float4* __restrict__ dstF,
             const float4* __restrict__ srcB, float4* __restrict__ dstB,
             int dx, int dy, int rsIdx, int stage0, int last) {
    int hid = blockIdx.x >> 6;
    int p   = ((blockIdx.x & 63) << 8) | threadIdx.x;
    int b = p >> 12, h = (p >> 6) & 63, w = p & 63;
    int fwd = (hid == 0);

    int sy, sx;
    const float* base;
    if (fwd) { sy = 64; sx = 1; base = corr + (size_t)p * 4096; }
    else     { sy = 262144; sx = 4096; base = corr + (size_t)b * 16777216 + h * 64 + w; }

    const float4* src = fwd ? srcF : srcB;
    float4*       dst = fwd ? dstF : dstB;
    const float*  m   = fwd ? mf : mb;

    // neighbor pixel indices
    int ph = (p & ~63) | ((w - dx) & 63);
    int pv = (b << 12) | (((h - dy) & 63) << 6) | w;

    float2 cur, ch, cv;
    float cur_s;

    if (stage0) {
        int mb8 = b * 8192;
        // incumbent + both neighbors straight from the (transposed-view) input
        cur = make_float2(m[mb8 + (p  & 4095)], m[mb8 + 4096 + (p  & 4095)]);
        ch  = make_float2(m[mb8 + (ph & 4095)], m[mb8 + 4096 + (ph & 4095)]);
        cv  = make_float2(m[mb8 + (pv & 4095)], m[mb8 + 4096 + (pv & 4095)]);
        cur_s = score(base, sy, sx, cur.x, cur.y);
    } else {
        float4 st = src[p];
        float4 sh = src[ph];
        float4 sv = src[pv];
        cur = make_float2(st.x, st.y); cur_s = st.z;
        ch  = make_float2(sh.x, sh.y);
        cv  = make_float2(sv.x, sv.y);
    }

    // horizontal candidate
    ch.x = fminf(fmaxf(ch.x + (float)dx, 0.0f), 63.0f);
    ch.y = fminf(fmaxf(ch.y, 0.0f), 63.0f);
    // vertical candidate
    cv.y = fminf(fmaxf(cv.y + (float)dy, 0.0f), 63.0f);
    cv.x = fminf(fmaxf(cv.x, 0.0f), 63.0f);

    float sH = score(base, sy, sx, ch.x, ch.y);
    float sV = score(base, sy, sx, cv.x, cv.y);

    if (sH > cur_s) { cur = ch; cur_s = sH; }  // candidate order matters
    if (sV > cur_s) { cur = cv; cur_s = sV; }

    if (last) {
        g_res[hid][p] = cur;
        return;
    }

    // ---- random search ----
    uint32_t K0, K1;
    get_rs_key(fwd, rsIdx, K0, K1);
    float n0 = normal_from_bits(random_bits(K0, K1, 2u * (uint32_t)p));
    float n1 = normal_from_bits(random_bits(K0, K1, 2u * (uint32_t)p + 1u));
    float2 cn;
    cn.x = fminf(fmaxf(cur.x + 3.0f * n0, 0.0f), 63.0f);
    cn.y = fminf(fmaxf(cur.y + 3.0f * n1, 0.0f), 63.0f);
    float new_s = score(base, sy, sx, cn.x, cn.y);
    if (new_s - 1.0f * cur_s > 0.0f) { cur = cn; cur_s = new_s; }

    dst[p] = make_float4(cur.x, cur.y, cur_s, 0.0f);
}

// ---------------------------------------------------------------------------
// Forward-backward consistency + output transpose
// ---------------------------------------------------------------------------
__global__ void __launch_bounds__(256)
final_kernel(const float* __restrict__ mf, float* __restrict__ out) {
    int p = blockIdx.x * blockDim.x + threadIdx.x;
    int b = p >> 12, hw = p & 4095;

    float2 f = g_res[0][p];
    float x0f = floorf(f.x), y0f = floorf(f.y);
    float wx = f.x - x0f, wy = f.y - y0f;
    int x0i = min(max((int)x0f, 0), 63);
    int x1i = min(x0i + 1, 63);
    int y0i = min(max((int)y0f, 0), 63);
    int y1i = min(y0i + 1, 63);
    const float2* img = g_res[1] + (b << 12);
    float2 v00 = img[y0i * 64 + x0i];
    float2 v01 = img[y0i * 64 + x1i];
    float2 v10 = img[y1i * 64 + x0i];
    float2 v11 = img[y1i * 64 + x1i];
    float cx = v00.x * (1.0f - wx) * (1.0f - wy) + v01.x * wx * (1.0f - wy)
             + v10.x * (1.0f - wx) * wy          + v11.x * wx * wy;
    float cy = v00.y * (1.0f - wx) * (1.0f - wy) + v01.y * wx * (1.0f - wy)
             + v10.y * (1.0f - wx) * wy          + v11.y * wx * wy;

    float diff = fmaxf(fabsf(f.x - cx), fabsf(f.y - cy));
    bool invalid = diff > 0.01f;
    float ox = invalid ? mf[b * 8192 + hw]        : f.x;
    float oy = invalid ? mf[b * 8192 + 4096 + hw] : f.y;
    out[b * 8192 + hw]        = ox;
    out[b * 8192 + 4096 + hw] = oy;
}

// ---------------------------------------------------------------------------
// Host launcher: 5 launches, both handles concurrent inside each stage kernel
// ---------------------------------------------------------------------------
extern "C" void kernel_launch(void* const* d_in, const int* in_sizes, int n_in,
                              void* d_out, int out_size) {
    const float* mf   = (const float*)d_in[0];
    const float* mb   = (const float*)d_in[1];
    const float* corr = (const float*)d_in[2];
    float* out = (float*)d_out;

    float4* st;
    cudaGetSymbolAddress((void**)&st, g_st);
    float4* F0 = st;                 // g_st[0][0]
    float4* F1 = st + NPIX;          // g_st[0][1]
    float4* B0 = st + 2 * NPIX;      // g_st[1][0]
    float4* B1 = st + 3 * NPIX;      // g_st[1][1]

    // stage 0: init + prop(1,1)  + rs0   (neighbors read straight from m)
    stage_kernel<<<128, 256>>>(mf, mb, corr, nullptr, F0, nullptr, B0,
                               1, 1, 0, 1, 0);
    // stage 1: prop(-1,-1) + rs1
    stage_kernel<<<128, 256>>>(mf, mb, corr, F0, F1, B0, B1,
                               -1, -1, 1, 0, 0);
    // stage 2: prop(-1,1) + rs2
    stage_kernel<<<128, 256>>>(mf, mb, corr, F1, F0, B1, B0,
                               -1, 1, 2, 0, 0);
    // stage 3: prop(1,-1) -> g_res
    stage_kernel<<<128, 256>>>(mf, mb, corr, F0, nullptr, B0, nullptr,
                               1, -1, 0, 0, 1);
    // consistency + output
    final_kernel<<<64, 256>>>(mf, out);
}